// round 6
// baseline (speedup 1.0000x reference)
#include <cuda_runtime.h>
#include <stdint.h>

#define NODES 50000
#define EDGES 800000
#define DD    128
#define EPS   1e-5f

// ---------------- scratch (static device globals; no allocation) ----------------
__device__ float g_agg[(size_t)NODES * DD];
__device__ float g_h1[(size_t)NODES * DD];   // pre-BN layer output
__device__ float g_h2[(size_t)NODES * DD];   // post-BN layer output
__device__ float g_rdeg[NODES];
__device__ int   g_deg[NODES];
__device__ int   g_csr_ptr[NODES + 1];
__device__ int   g_cursor[NODES];
__device__ int   g_csr_src[EDGES];
__device__ int   g_bsum[256];
__device__ int   g_boff[256];
__device__ float g_stats[2 * DD];            // [0:128) col sums, [128:256) sumsq

// ---------------- degree + CSR build ----------------
__global__ void k_zero_deg(int n) {
    int i = blockIdx.x * blockDim.x + threadIdx.x;
    if (i < n) g_deg[i] = 0;
}

__global__ void k_count_deg(const int* __restrict__ dst, int e) {
    int i = blockIdx.x * blockDim.x + threadIdx.x;
    if (i < e) atomicAdd(&g_deg[dst[i]], 1);
}

// exclusive scan, pass 1: per-block scan + block sums
__global__ void k_scan1(int n) {
    __shared__ int s[256];
    int tid = threadIdx.x;
    int i = blockIdx.x * 256 + tid;
    int v = (i < n) ? g_deg[i] : 0;
    s[tid] = v;
    __syncthreads();
#pragma unroll
    for (int o = 1; o < 256; o <<= 1) {
        int x = (tid >= o) ? s[tid - o] : 0;
        __syncthreads();
        s[tid] += x;
        __syncthreads();
    }
    if (i < n) g_csr_ptr[i] = s[tid] - v;   // block-local exclusive
    if (tid == 255) g_bsum[blockIdx.x] = s[255];
}

// pass 2: single-block exclusive scan of block sums
__global__ void k_scan2(int nb) {
    __shared__ int s[256];
    int tid = threadIdx.x;
    int v = (tid < nb) ? g_bsum[tid] : 0;
    s[tid] = v;
    __syncthreads();
#pragma unroll
    for (int o = 1; o < 256; o <<= 1) {
        int x = (tid >= o) ? s[tid - o] : 0;
        __syncthreads();
        s[tid] += x;
        __syncthreads();
    }
    if (tid < nb) g_boff[tid] = s[tid] - v;
}

// pass 3: add offsets, init cursor, rdeg, sentinel
__global__ void k_scan3(int n, int e) {
    int i = blockIdx.x * blockDim.x + threadIdx.x;
    if (i < n) {
        int p = g_csr_ptr[i] + g_boff[blockIdx.x];
        g_csr_ptr[i] = p;
        g_cursor[i] = p;
        int d = g_deg[i];
        g_rdeg[i] = 1.0f / (float)(d > 0 ? d : 1);
    }
    if (i == 0) g_csr_ptr[n] = e;
}

__global__ void k_fill(const int* __restrict__ src, const int* __restrict__ dst, int e) {
    int i = blockIdx.x * blockDim.x + threadIdx.x;
    if (i < e) {
        int pos = atomicAdd(&g_cursor[dst[i]], 1);
        g_csr_src[pos] = src[i];
    }
}

// ---------------- gather: one warp per dst node, mean of neighbor rows ----------------
__global__ __launch_bounds__(256)
void k_gather(const float* __restrict__ h, int n) {
    int node = (blockIdx.x * blockDim.x + threadIdx.x) >> 5;
    int lane = threadIdx.x & 31;
    if (node >= n) return;
    int beg = g_csr_ptr[node];
    int end = g_csr_ptr[node + 1];
    float4 acc = make_float4(0.f, 0.f, 0.f, 0.f);
    for (int base = beg; base < end; base += 32) {
        int mye = base + lane;
        int sidx = (mye < end) ? g_csr_src[mye] : 0;
        int cnt = min(32, end - base);
        int i = 0;
        for (; i + 1 < cnt; i += 2) {
            int s0 = __shfl_sync(0xffffffffu, sidx, i);
            int s1 = __shfl_sync(0xffffffffu, sidx, i + 1);
            float4 v0 = *reinterpret_cast<const float4*>(h + (size_t)s0 * DD + lane * 4);
            float4 v1 = *reinterpret_cast<const float4*>(h + (size_t)s1 * DD + lane * 4);
            acc.x += v0.x; acc.y += v0.y; acc.z += v0.z; acc.w += v0.w;
            acc.x += v1.x; acc.y += v1.y; acc.z += v1.z; acc.w += v1.w;
        }
        if (i < cnt) {
            int s0 = __shfl_sync(0xffffffffu, sidx, i);
            float4 v0 = *reinterpret_cast<const float4*>(h + (size_t)s0 * DD + lane * 4);
            acc.x += v0.x; acc.y += v0.y; acc.z += v0.z; acc.w += v0.w;
        }
    }
    float rd = g_rdeg[node];
    acc.x *= rd; acc.y *= rd; acc.z *= rd; acc.w *= rd;
    *reinterpret_cast<float4*>(g_agg + (size_t)node * DD + lane * 4) = acc;
}

// ---------------- tf32 tensor-core dual GEMM + bias + residual ----------------
__device__ __forceinline__ uint32_t f2tf32(float x) {
    uint32_t r;
    asm("cvt.rna.tf32.f32 %0, %1;" : "=r"(r) : "f"(x));
    return r;
}

__device__ __forceinline__ void mma_tf32(float* d, const uint32_t* a, const uint32_t* b) {
    asm volatile(
        "mma.sync.aligned.m16n8k8.row.col.f32.tf32.tf32.f32 "
        "{%0,%1,%2,%3}, {%4,%5,%6,%7}, {%8,%9}, {%0,%1,%2,%3};\n"
        : "+f"(d[0]), "+f"(d[1]), "+f"(d[2]), "+f"(d[3])
        : "r"(a[0]), "r"(a[1]), "r"(a[2]), "r"(a[3]), "r"(b[0]), "r"(b[1]));
}

// Block: 128x128 output tile, 256 threads = 8 warps (4 m x 2 n), warp tile 32x64.
// out[m,n] = h@Ws + (agg)@Wn + bias[n] + h[m,n]   (agg already scaled by rdeg)
#define BM 128
#define BK 16
#define A_STRIDE 20
#define B_STRIDE 136

__global__ __launch_bounds__(256, 2)
void k_gemm_tc(const float* __restrict__ h,
               const float* __restrict__ Ws, const float* __restrict__ Wn,
               const float* __restrict__ bias, float* __restrict__ out, int nrows) {
    __shared__ uint32_t Ah[128][A_STRIDE];
    __shared__ uint32_t Aa[128][A_STRIDE];
    __shared__ uint32_t Bs[BK][B_STRIDE];
    __shared__ uint32_t Bn[BK][B_STRIDE];

    const int tid  = threadIdx.x;
    const int warp = tid >> 5;
    const int lane = tid & 31;
    const int g    = lane >> 2;      // 0..7
    const int t    = lane & 3;       // 0..3
    const int wm   = warp & 3;       // 0..3
    const int wn   = warp >> 2;      // 0..1
    const int m0   = blockIdx.x * BM;
    const int wrow = wm * 32;
    const int wcol = wn * 64;

    float acc[2][8][4];
#pragma unroll
    for (int mt = 0; mt < 2; mt++)
#pragma unroll
        for (int nt = 0; nt < 8; nt++)
#pragma unroll
            for (int j = 0; j < 4; j++) acc[mt][nt][j] = 0.f;

    for (int kc = 0; kc < DD / BK; kc++) {
        const int ks = kc * BK;
        // A tiles: 128x16 = 512 float4, 2 per thread (both matrices)
#pragma unroll
        for (int r = 0; r < 2; r++) {
            int id  = tid + r * 256;      // 0..511
            int row = id >> 2;            // 0..127
            int c4  = id & 3;             // 0..3
            int grow = m0 + row;
            float4 vh = make_float4(0.f, 0.f, 0.f, 0.f);
            float4 va = make_float4(0.f, 0.f, 0.f, 0.f);
            if (grow < nrows) {
                size_t off = (size_t)grow * DD + ks + c4 * 4;
                vh = *reinterpret_cast<const float4*>(h + off);
                va = *reinterpret_cast<const float4*>(g_agg + off);
            }
            uint4 ph = make_uint4(f2tf32(vh.x), f2tf32(vh.y), f2tf32(vh.z), f2tf32(vh.w));
            uint4 pa = make_uint4(f2tf32(va.x), f2tf32(va.y), f2tf32(va.z), f2tf32(va.w));
            *reinterpret_cast<uint4*>(&Ah[row][c4 * 4]) = ph;
            *reinterpret_cast<uint4*>(&Aa[row][c4 * 4]) = pa;
        }
        // B tiles: 16x128 = 512 float4, 2 per thread (both matrices)
#pragma unroll
        for (int r = 0; r < 2; r++) {
            int id  = tid + r * 256;      // 0..511
            int row = id >> 5;            // 0..15
            int c4  = id & 31;            // 0..31
            size_t off = (size_t)(ks + row) * DD + c4 * 4;
            float4 vs = *reinterpret_cast<const float4*>(Ws + off);
            float4 vn = *reinterpret_cast<const float4*>(Wn + off);
            uint4 ps = make_uint4(f2tf32(vs.x), f2tf32(vs.y), f2tf32(vs.z), f2tf32(vs.w));
            uint4 pn = make_uint4(f2tf32(vn.x), f2tf32(vn.y), f2tf32(vn.z), f2tf32(vn.w));
            *reinterpret_cast<uint4*>(&Bs[row][c4 * 4]) = ps;
            *reinterpret_cast<uint4*>(&Bn[row][c4 * 4]) = pn;
        }
        __syncthreads();

#pragma unroll
        for (int ks8 = 0; ks8 < BK / 8; ks8++) {
            const int kb = ks8 * 8;
            uint32_t a[2][4], b[8][2];
            // term 1: h @ Ws
#pragma unroll
            for (int mt = 0; mt < 2; mt++) {
                int r = wrow + mt * 16;
                a[mt][0] = Ah[r + g][kb + t];
                a[mt][1] = Ah[r + g + 8][kb + t];
                a[mt][2] = Ah[r + g][kb + t + 4];
                a[mt][3] = Ah[r + g + 8][kb + t + 4];
            }
#pragma unroll
            for (int nt = 0; nt < 8; nt++) {
                int c = wcol + nt * 8 + g;
                b[nt][0] = Bs[kb + t][c];
                b[nt][1] = Bs[kb + t + 4][c];
            }
#pragma unroll
            for (int mt = 0; mt < 2; mt++)
#pragma unroll
                for (int nt = 0; nt < 8; nt++)
                    mma_tf32(acc[mt][nt], a[mt], b[nt]);
            // term 2: agg @ Wn
#pragma unroll
            for (int mt = 0; mt < 2; mt++) {
                int r = wrow + mt * 16;
                a[mt][0] = Aa[r + g][kb + t];
                a[mt][1] = Aa[r + g + 8][kb + t];
                a[mt][2] = Aa[r + g][kb + t + 4];
                a[mt][3] = Aa[r + g + 8][kb + t + 4];
            }
#pragma unroll
            for (int nt = 0; nt < 8; nt++) {
                int c = wcol + nt * 8 + g;
                b[nt][0] = Bn[kb + t][c];
                b[nt][1] = Bn[kb + t + 4][c];
            }
#pragma unroll
            for (int mt = 0; mt < 2; mt++)
#pragma unroll
                for (int nt = 0; nt < 8; nt++)
                    mma_tf32(acc[mt][nt], a[mt], b[nt]);
        }
        __syncthreads();
    }

    // epilogue: + bias + residual, write out (float2 pairs c0/c1, c2/c3)
#pragma unroll
    for (int mt = 0; mt < 2; mt++) {
#pragma unroll
        for (int rr = 0; rr < 2; rr++) {
            int grow = m0 + wrow + mt * 16 + g + rr * 8;
            if (grow < nrows) {
#pragma unroll
                for (int nt = 0; nt < 8; nt++) {
                    int col = wcol + nt * 8 + t * 2;
                    size_t off = (size_t)grow * DD + col;
                    float2 res = *reinterpret_cast<const float2*>(h + off);
                    float2 bv  = *reinterpret_cast<const float2*>(bias + col);
                    float2 o;
                    o.x = acc[mt][nt][rr * 2 + 0] + bv.x + res.x;
                    o.y = acc[mt][nt][rr * 2 + 1] + bv.y + res.y;
                    *reinterpret_cast<float2*>(out + off) = o;
                }
            }
        }
    }
}

// ---------------- column stats (sum, sumsq) for BN ----------------
__global__ __launch_bounds__(256)
void k_stats(const float* __restrict__ x, int n) {
    __shared__ float sh[8][DD];
    __shared__ float shq[8][DD];
    int lane = threadIdx.x & 31;
    int w    = threadIdx.x >> 5;
    int c    = lane * 4;
    float4 s = make_float4(0.f, 0.f, 0.f, 0.f);
    float4 q = make_float4(0.f, 0.f, 0.f, 0.f);
    for (int r = blockIdx.x * 8 + w; r < n; r += gridDim.x * 8) {
        float4 v = *reinterpret_cast<const float4*>(x + (size_t)r * DD + c);
        s.x += v.x; s.y += v.y; s.z += v.z; s.w += v.w;
        q.x += v.x * v.x; q.y += v.y * v.y; q.z += v.z * v.z; q.w += v.w * v.w;
    }
    *reinterpret_cast<float4*>(&sh[w][c])  = s;
    *reinterpret_cast<float4*>(&shq[w][c]) = q;
    __syncthreads();
    if (threadIdx.x < DD) {
        float ss = 0.f, qq = 0.f;
#pragma unroll
        for (int r = 0; r < 8; r++) { ss += sh[r][threadIdx.x]; qq += shq[r][threadIdx.x]; }
        atomicAdd(&g_stats[threadIdx.x], ss);
        atomicAdd(&g_stats[DD + threadIdx.x], qq);
    }
}

// ---------------- BN (train-mode, biased var) + ReLU ----------------
__global__ void k_bn_relu(const float* __restrict__ hn, const float* __restrict__ gamma,
                          const float* __restrict__ beta, float* __restrict__ out, int n) {
    int idx   = blockIdx.x * blockDim.x + threadIdx.x;
    int total = n * (DD / 4);
    if (idx >= total) return;
    int c4 = idx & 31;
    int c  = c4 * 4;
    float inv = 1.0f / (float)n;

    float4 v = reinterpret_cast<const float4*>(hn)[idx];
    float4 o;
#define BN_ONE(comp, cc)                                            \
    {                                                               \
        float mu  = g_stats[cc] * inv;                              \
        float var = g_stats[DD + cc] * inv - mu * mu;               \
        float sc  = rsqrtf(var + EPS) * __ldg(gamma + cc);          \
        float sh  = __ldg(beta + cc) - mu * sc;                     \
        o.comp = fmaxf(fmaf(v.comp, sc, sh), 0.f);                  \
    }
    BN_ONE(x, c + 0)
    BN_ONE(y, c + 1)
    BN_ONE(z, c + 2)
    BN_ONE(w, c + 3)
#undef BN_ONE
    reinterpret_cast<float4*>(out)[idx] = o;
}

// ---------------- launch ----------------
extern "C" void kernel_launch(void* const* d_in, const int* in_sizes, int n_in,
                              void* d_out, int out_size) {
    const float* feat   = (const float*)d_in[0];
    const int*   src    = (const int*)d_in[1];
    const int*   dst    = (const int*)d_in[2];
    const float* Wself  = (const float*)d_in[3];
    const float* Wneigh = (const float*)d_in[4];
    const float* bias   = (const float*)d_in[5];
    const float* gamma  = (const float*)d_in[6];
    const float* beta   = (const float*)d_in[7];
    float* out = (float*)d_out;

    const int N = in_sizes[0] / DD;
    const int E = in_sizes[1];

    void *p_h1, *p_h2, *p_stats;
    cudaGetSymbolAddress(&p_h1, g_h1);
    cudaGetSymbolAddress(&p_h2, g_h2);
    cudaGetSymbolAddress(&p_stats, g_stats);

    // ---- CSR build (once per launch) ----
    const int nb = (N + 255) / 256;
    k_zero_deg<<<nb, 256>>>(N);
    k_count_deg<<<(E + 255) / 256, 256>>>(dst, E);
    k_scan1<<<nb, 256>>>(N);
    k_scan2<<<1, 256>>>(nb);
    k_scan3<<<nb, 256>>>(N, E);
    k_fill<<<(E + 255) / 256, 256>>>(src, dst, E);

    const int gemm_blocks   = (N + BM - 1) / BM;
    const int gather_blocks = (N + 7) / 8;       // warp per node, 8 warps/block
    const int bn_blocks     = (N * (DD / 4) + 255) / 256;

    const float* hcur = feat;
    for (int l = 0; l < 3; l++) {
        k_gather<<<gather_blocks, 256>>>(hcur, N);

        const float* Ws = Wself + (size_t)l * DD * DD;
        const float* Wn = Wneigh + (size_t)l * DD * DD;
        const float* bl = bias + (size_t)l * DD;

        if (l < 2) {
            cudaMemsetAsync(p_stats, 0, 2 * DD * sizeof(float), 0);
            k_gemm_tc<<<gemm_blocks, 256>>>(hcur, Ws, Wn, bl, (float*)p_h1, N);
            k_stats<<<128, 256>>>((const float*)p_h1, N);
            k_bn_relu<<<bn_blocks, 256>>>((const float*)p_h1,
                                          gamma + (size_t)l * DD,
                                          beta + (size_t)l * DD,
                                          (float*)p_h2, N);
            hcur = (const float*)p_h2;
        } else {
            k_gemm_tc<<<gemm_blocks, 256>>>(hcur, Ws, Wn, bl, out, N);
        }
    }
    (void)n_in; (void)out_size;
}